// round 5
// baseline (speedup 1.0000x reference)
#include <cuda_runtime.h>
#include <math.h>
#include <float.h>

#define Nn   2048
#define DIN  256
#define DIM  256
#define NH   8
#define CH   32
#define TOPK 16

// ---------------- device scratch (static, allocation-free) ----------------
__device__ float g_x[Nn * DIN];                 // LN1 output
__device__ float g_qkv[Nn * 3 * DIM];           // qkv, row-major [N][768]
__device__ float g_S[(size_t)NH * Nn * Nn];     // per-head scores -> A (128 MB)
__device__ float g_msg[Nn * DIM];               // attention message
__device__ float g_msg2[Nn * DIM];              // after proj + residual

// ---------------- LayerNorm (one block per row, 256 cols) ----------------
__global__ void ln_kernel(const float* __restrict__ in,
                          const float* __restrict__ w,
                          const float* __restrict__ b,
                          float* __restrict__ out) {
    __shared__ float red[256];
    int row = blockIdx.x, t = threadIdx.x;
    float v = in[row * 256 + t];
    red[t] = v; __syncthreads();
    for (int s = 128; s > 0; s >>= 1) { if (t < s) red[t] += red[t + s]; __syncthreads(); }
    float mu = red[0] * (1.0f / 256.0f);
    __syncthreads();
    float d = v - mu;
    red[t] = d * d; __syncthreads();
    for (int s = 128; s > 0; s >>= 1) { if (t < s) red[t] += red[t + s]; __syncthreads(); }
    float var = red[0] * (1.0f / 256.0f);
    out[row * 256 + t] = d * rsqrtf(var + 1e-5f) * w[t] + b[t];
}

// ---------------- SGEMM: C[M,NC] = A[M,K] @ B[K,NC] (64x64 tile) ----------
__global__ void sgemm_qkv(const float* __restrict__ A, const float* __restrict__ B,
                          float* __restrict__ C, int M, int K, int NC) {
    __shared__ float As[16][64];
    __shared__ float Bs[16][64];
    int tid = threadIdx.x;
    int tx = tid % 16, ty = tid / 16;
    int m0 = blockIdx.y * 64, n0 = blockIdx.x * 64;
    float acc[4][4] = {};
    for (int k0 = 0; k0 < K; k0 += 16) {
        for (int i = tid; i < 64 * 16; i += 256) {
            int m = i / 16, k = i % 16;
            As[k][m] = A[(size_t)(m0 + m) * K + k0 + k];
        }
        for (int i = tid; i < 16 * 64; i += 256) {
            int k = i / 64, n = i % 64;
            Bs[k][n] = B[(size_t)(k0 + k) * NC + n0 + n];
        }
        __syncthreads();
        #pragma unroll
        for (int k = 0; k < 16; k++) {
            float a[4], bb[4];
            #pragma unroll
            for (int i = 0; i < 4; i++) a[i] = As[k][ty * 4 + i];
            #pragma unroll
            for (int j = 0; j < 4; j++) bb[j] = Bs[k][tx * 4 + j];
            #pragma unroll
            for (int i = 0; i < 4; i++)
                #pragma unroll
                for (int j = 0; j < 4; j++) acc[i][j] += a[i] * bb[j];
        }
        __syncthreads();
    }
    for (int i = 0; i < 4; i++)
        for (int j = 0; j < 4; j++)
            C[(size_t)(m0 + ty * 4 + i) * NC + n0 + tx * 4 + j] = acc[i][j];
}

// ---------------- proj GEMM with bias + residual(v) epilogue --------------
__global__ void sgemm_proj(const float* __restrict__ A, const float* __restrict__ B,
                           const float* __restrict__ bias, const float* __restrict__ qkv,
                           float* __restrict__ C) {
    // M=2048, K=256, NC=256
    __shared__ float As[16][64];
    __shared__ float Bs[16][64];
    int tid = threadIdx.x;
    int tx = tid % 16, ty = tid / 16;
    int m0 = blockIdx.y * 64, n0 = blockIdx.x * 64;
    float acc[4][4] = {};
    for (int k0 = 0; k0 < 256; k0 += 16) {
        for (int i = tid; i < 64 * 16; i += 256) {
            int m = i / 16, k = i % 16;
            As[k][m] = A[(m0 + m) * 256 + k0 + k];
        }
        for (int i = tid; i < 16 * 64; i += 256) {
            int k = i / 64, n = i % 64;
            Bs[k][n] = B[(k0 + k) * 256 + n0 + n];
        }
        __syncthreads();
        #pragma unroll
        for (int k = 0; k < 16; k++) {
            float a[4], bb[4];
            #pragma unroll
            for (int i = 0; i < 4; i++) a[i] = As[k][ty * 4 + i];
            #pragma unroll
            for (int j = 0; j < 4; j++) bb[j] = Bs[k][tx * 4 + j];
            #pragma unroll
            for (int i = 0; i < 4; i++)
                #pragma unroll
                for (int j = 0; j < 4; j++) acc[i][j] += a[i] * bb[j];
        }
        __syncthreads();
    }
    for (int i = 0; i < 4; i++)
        for (int j = 0; j < 4; j++) {
            int m = m0 + ty * 4 + i, n = n0 + tx * 4 + j;
            C[m * 256 + n] = acc[i][j] + bias[n] + qkv[m * 768 + 512 + n];
        }
}

// ---------------- per-head QK^T * scale -> g_S ----------------------------
__global__ void qk_kernel(const float* __restrict__ qkv) {
    __shared__ float Qs[32][64];
    __shared__ float Ks[32][64];
    int tid = threadIdx.x;
    int h = blockIdx.z;
    int l0 = blockIdx.y * 64, s0 = blockIdx.x * 64;
    for (int i = tid; i < 64 * 32; i += 256) {
        int r = i / 32, d = i % 32;
        Qs[d][r] = qkv[(l0 + r) * 768 + h * 32 + d];
        Ks[d][r] = qkv[(s0 + r) * 768 + 256 + h * 32 + d];
    }
    __syncthreads();
    int tx = tid % 16, ty = tid / 16;
    float acc[4][4] = {};
    #pragma unroll
    for (int d = 0; d < 32; d++) {
        float a[4], b[4];
        #pragma unroll
        for (int i = 0; i < 4; i++) a[i] = Qs[d][ty * 4 + i];
        #pragma unroll
        for (int j = 0; j < 4; j++) b[j] = Ks[d][tx * 4 + j];
        #pragma unroll
        for (int i = 0; i < 4; i++)
            #pragma unroll
            for (int j = 0; j < 4; j++) acc[i][j] += a[i] * b[j];
    }
    const float scale = 0.1767766952966369f; // 1/sqrt(32)
    float* Sp = g_S + ((size_t)h * Nn + l0) * Nn + s0;
    for (int i = 0; i < 4; i++)
        for (int j = 0; j < 4; j++)
            Sp[(size_t)(ty * 4 + i) * Nn + tx * 4 + j] = acc[i][j] * scale;
}

// ---------------- row softmax in place ------------------------------------
__global__ void softmax_kernel() {
    int l = blockIdx.x, h = blockIdx.y, t = threadIdx.x;
    float* row = g_S + ((size_t)h * Nn + l) * Nn;
    float vals[8];
    float mx = -FLT_MAX;
    #pragma unroll
    for (int i = 0; i < 8; i++) { vals[i] = row[t + i * 256]; mx = fmaxf(mx, vals[i]); }
    __shared__ float red[256];
    red[t] = mx; __syncthreads();
    for (int s = 128; s > 0; s >>= 1) { if (t < s) red[t] = fmaxf(red[t], red[t + s]); __syncthreads(); }
    mx = red[0]; __syncthreads();
    float sum = 0.0f;
    #pragma unroll
    for (int i = 0; i < 8; i++) { vals[i] = expf(vals[i] - mx); sum += vals[i]; }
    red[t] = sum; __syncthreads();
    for (int s = 128; s > 0; s >>= 1) { if (t < s) red[t] += red[t + s]; __syncthreads(); }
    float inv = 1.0f / red[0];
    #pragma unroll
    for (int i = 0; i < 8; i++) row[t + i * 256] = vals[i] * inv;
}

// ---------------- head-mean + iterative top-16 per row --------------------
__global__ void topk_kernel(float* __restrict__ out_idx) {
    __shared__ float am[2048];
    __shared__ float sv[256];
    __shared__ int   si[256];
    int l = blockIdx.x, t = threadIdx.x;
    #pragma unroll
    for (int i = 0; i < 8; i++) {
        int c = t + i * 256;
        float s = 0.0f;
        #pragma unroll
        for (int h = 0; h < 8; h++) s += g_S[((size_t)h * Nn + l) * Nn + c];
        am[c] = s * 0.125f;
    }
    __syncthreads();
    for (int j = 0; j < TOPK; j++) {
        float bv = -FLT_MAX; int bi = 0x7fffffff;
        #pragma unroll
        for (int i = 0; i < 8; i++) {
            int c = t + i * 256;
            float v = am[c];
            if (v > bv || (v == bv && c < bi)) { bv = v; bi = c; }
        }
        sv[t] = bv; si[t] = bi; __syncthreads();
        for (int s = 128; s > 0; s >>= 1) {
            if (t < s) {
                if (sv[t + s] > sv[t] || (sv[t + s] == sv[t] && si[t + s] < si[t])) {
                    sv[t] = sv[t + s]; si[t] = si[t + s];
                }
            }
            __syncthreads();
        }
        if (t == 0) {
            out_idx[l * TOPK + j] = (float)si[0];
            am[si[0]] = -FLT_MAX;
        }
        __syncthreads();
    }
}

// ---------------- per-head A @ V -> message --------------------------------
__global__ void av_kernel(const float* __restrict__ qkv) {
    __shared__ float At[64][64];
    __shared__ float Vt[64][32];
    int tid = threadIdx.x;
    int h = blockIdx.y, l0 = blockIdx.x * 64;
    int col = tid % 32, rg = tid / 32; // rg in [0,8)
    float acc[8] = {};
    for (int s0 = 0; s0 < Nn; s0 += 64) {
        for (int i = tid; i < 64 * 64; i += 256) {
            int r = i / 64, c = i % 64;
            At[r][c] = g_S[((size_t)h * Nn + l0 + r) * Nn + s0 + c];
        }
        for (int i = tid; i < 64 * 32; i += 256) {
            int s = i / 32, d = i % 32;
            Vt[s][d] = qkv[(s0 + s) * 768 + 512 + h * 32 + d];
        }
        __syncthreads();
        #pragma unroll
        for (int st = 0; st < 64; st++) {
            float vv = Vt[st][col];
            #pragma unroll
            for (int r = 0; r < 8; r++) acc[r] += At[rg * 8 + r][st] * vv;
        }
        __syncthreads();
    }
    #pragma unroll
    for (int r = 0; r < 8; r++)
        g_msg[(l0 + rg * 8 + r) * 256 + h * 32 + col] = acc[r];
}

// ---------------- launch ----------------------------------------------------
extern "C" void kernel_launch(void* const* d_in, const int* in_sizes, int n_in,
                              void* d_out, int out_size) {
    const float* point  = (const float*)d_in[0];
    const float* w_qkv  = (const float*)d_in[1];
    const float* w_proj = (const float*)d_in[2];
    const float* b_proj = (const float*)d_in[3];
    const float* n1w    = (const float*)d_in[4];
    const float* n1b    = (const float*)d_in[5];
    const float* n2w    = (const float*)d_in[6];
    const float* n2b    = (const float*)d_in[7];
    float* out = (float*)d_out;

    float *p_x, *p_qkv, *p_msg, *p_msg2;
    cudaGetSymbolAddress((void**)&p_x,    g_x);
    cudaGetSymbolAddress((void**)&p_qkv,  g_qkv);
    cudaGetSymbolAddress((void**)&p_msg,  g_msg);
    cudaGetSymbolAddress((void**)&p_msg2, g_msg2);

    // 1. LN1
    ln_kernel<<<Nn, 256>>>(point, n1w, n1b, p_x);
    // 2. QKV GEMM: [2048,256] @ [256,768]
    sgemm_qkv<<<dim3(768 / 64, Nn / 64), 256>>>(p_x, w_qkv, p_qkv, Nn, 256, 768);
    // 3. per-head scores
    qk_kernel<<<dim3(Nn / 64, Nn / 64, NH), 256>>>(p_qkv);
    // 4. softmax rows
    softmax_kernel<<<dim3(Nn, NH), 256>>>();
    // 5. head-mean + topk -> indices region of d_out
    if (out_size >= Nn * DIM + Nn * TOPK)
        topk_kernel<<<Nn, 256>>>(out + Nn * DIM);
    // 6. A @ V
    av_kernel<<<dim3(Nn / 64, NH), 256>>>(p_qkv);
    // 7. proj + bias + residual(v)
    sgemm_proj<<<dim3(256 / 64, Nn / 64), 256>>>(p_msg, w_proj, b_proj, p_qkv, p_msg2);
    // 8. LN2 -> main output region
    ln_kernel<<<Nn, 256>>>(p_msg2, n2w, n2b, out);
}

// round 9
// speedup vs baseline: 1.2458x; 1.2458x over previous
#include <cuda_runtime.h>
#include <math.h>
#include <float.h>

#define Nn   2048
#define DIN  256
#define DIM  256
#define NH   8
#define CH   32
#define TOPK 16

// ---------------- device scratch (static, allocation-free) ----------------
__device__ float g_x[Nn * DIN];                 // LN1 output
__device__ float g_qkv[Nn * 3 * DIM];           // qkv, row-major [N][768]
__device__ float g_S[(size_t)NH * Nn * Nn];     // per-head scores -> A (128 MB)
__device__ float g_msg[Nn * DIM];               // attention message
__device__ float g_msg2[Nn * DIM];              // after proj + residual

// ---------------- warp reduce helpers --------------------------------------
__device__ __forceinline__ float warpMax(float v) {
    #pragma unroll
    for (int o = 16; o > 0; o >>= 1) v = fmaxf(v, __shfl_xor_sync(0xffffffffu, v, o));
    return v;
}
__device__ __forceinline__ float warpSum(float v) {
    #pragma unroll
    for (int o = 16; o > 0; o >>= 1) v += __shfl_xor_sync(0xffffffffu, v, o);
    return v;
}

// ---------------- LayerNorm (one block per row, 256 cols) ----------------
__global__ void ln_kernel(const float* __restrict__ in,
                          const float* __restrict__ w,
                          const float* __restrict__ b,
                          float* __restrict__ out) {
    __shared__ float red[256];
    int row = blockIdx.x, t = threadIdx.x;
    float v = in[row * 256 + t];
    red[t] = v; __syncthreads();
    for (int s = 128; s > 0; s >>= 1) { if (t < s) red[t] += red[t + s]; __syncthreads(); }
    float mu = red[0] * (1.0f / 256.0f);
    __syncthreads();
    float d = v - mu;
    red[t] = d * d; __syncthreads();
    for (int s = 128; s > 0; s >>= 1) { if (t < s) red[t] += red[t + s]; __syncthreads(); }
    float var = red[0] * (1.0f / 256.0f);
    out[row * 256 + t] = d * rsqrtf(var + 1e-5f) * w[t] + b[t];
}

// ---------------- SGEMM: C[M,NC] = A[M,K] @ B[K,NC] (64x64 tile) ----------
__global__ void sgemm_qkv(const float* __restrict__ A, const float* __restrict__ B,
                          float* __restrict__ C, int M, int K, int NC) {
    __shared__ float As[16][64];
    __shared__ float Bs[16][64];
    int tid = threadIdx.x;
    int tx = tid % 16, ty = tid / 16;
    int m0 = blockIdx.y * 64, n0 = blockIdx.x * 64;
    float acc[4][4] = {};
    for (int k0 = 0; k0 < K; k0 += 16) {
        for (int i = tid; i < 64 * 16; i += 256) {
            int m = i / 16, k = i % 16;
            As[k][m] = A[(size_t)(m0 + m) * K + k0 + k];
        }
        for (int i = tid; i < 16 * 64; i += 256) {
            int k = i / 64, n = i % 64;
            Bs[k][n] = B[(size_t)(k0 + k) * NC + n0 + n];
        }
        __syncthreads();
        #pragma unroll
        for (int k = 0; k < 16; k++) {
            float a[4], bb[4];
            #pragma unroll
            for (int i = 0; i < 4; i++) a[i] = As[k][ty * 4 + i];
            #pragma unroll
            for (int j = 0; j < 4; j++) bb[j] = Bs[k][tx * 4 + j];
            #pragma unroll
            for (int i = 0; i < 4; i++)
                #pragma unroll
                for (int j = 0; j < 4; j++) acc[i][j] += a[i] * bb[j];
        }
        __syncthreads();
    }
    for (int i = 0; i < 4; i++)
        for (int j = 0; j < 4; j++)
            C[(size_t)(m0 + ty * 4 + i) * NC + n0 + tx * 4 + j] = acc[i][j];
}

// ---------------- proj GEMM with bias + residual(v) epilogue --------------
__global__ void sgemm_proj(const float* __restrict__ A, const float* __restrict__ B,
                           const float* __restrict__ bias, const float* __restrict__ qkv,
                           float* __restrict__ C) {
    // M=2048, K=256, NC=256
    __shared__ float As[16][64];
    __shared__ float Bs[16][64];
    int tid = threadIdx.x;
    int tx = tid % 16, ty = tid / 16;
    int m0 = blockIdx.y * 64, n0 = blockIdx.x * 64;
    float acc[4][4] = {};
    for (int k0 = 0; k0 < 256; k0 += 16) {
        for (int i = tid; i < 64 * 16; i += 256) {
            int m = i / 16, k = i % 16;
            As[k][m] = A[(m0 + m) * 256 + k0 + k];
        }
        for (int i = tid; i < 16 * 64; i += 256) {
            int k = i / 64, n = i % 64;
            Bs[k][n] = B[(k0 + k) * 256 + n0 + n];
        }
        __syncthreads();
        #pragma unroll
        for (int k = 0; k < 16; k++) {
            float a[4], bb[4];
            #pragma unroll
            for (int i = 0; i < 4; i++) a[i] = As[k][ty * 4 + i];
            #pragma unroll
            for (int j = 0; j < 4; j++) bb[j] = Bs[k][tx * 4 + j];
            #pragma unroll
            for (int i = 0; i < 4; i++)
                #pragma unroll
                for (int j = 0; j < 4; j++) acc[i][j] += a[i] * bb[j];
        }
        __syncthreads();
    }
    for (int i = 0; i < 4; i++)
        for (int j = 0; j < 4; j++) {
            int m = m0 + ty * 4 + i, n = n0 + tx * 4 + j;
            C[m * 256 + n] = acc[i][j] + bias[n] + qkv[m * 768 + 512 + n];
        }
}

// ---------------- per-head QK^T * scale -> g_S (128x128 tiles) ------------
__global__ void __launch_bounds__(256) qk_kernel(const float* __restrict__ qkv) {
    __shared__ float Qs[128][33];
    __shared__ float Ks[128][33];
    int t = threadIdx.x;
    int h = blockIdx.z;
    int l0 = blockIdx.y * 128, s0 = blockIdx.x * 128;
    // coalesced global (consecutive d), conflict-free smem (row-major, pad 33)
    for (int i = t; i < 128 * 32; i += 256) {
        int r = i >> 5, d = i & 31;
        Qs[r][d] = qkv[(l0 + r) * 768 + h * 32 + d];
        Ks[r][d] = qkv[(s0 + r) * 768 + 256 + h * 32 + d];
    }
    __syncthreads();
    int tx = t & 15, ty = t >> 4;
    float acc[8][8] = {};
    #pragma unroll
    for (int d = 0; d < 32; d++) {
        float a[8], b[8];
        #pragma unroll
        for (int i = 0; i < 8; i++) a[i] = Qs[ty + i * 16][d];
        #pragma unroll
        for (int j = 0; j < 8; j++) b[j] = Ks[tx + j * 16][d];
        #pragma unroll
        for (int i = 0; i < 8; i++)
            #pragma unroll
            for (int j = 0; j < 8; j++) acc[i][j] += a[i] * b[j];
    }
    const float scale = 0.1767766952966369f; // 1/sqrt(32)
    float* Sp = g_S + ((size_t)h * Nn + l0) * Nn + s0;
    #pragma unroll
    for (int i = 0; i < 8; i++)
        #pragma unroll
        for (int j = 0; j < 8; j++)
            Sp[(size_t)(ty + i * 16) * Nn + tx + j * 16] = acc[i][j] * scale;
}

// ------- fused: softmax (all 8 heads of row l) + head-mean + top-16 -------
__global__ void softmax_mean_topk(float* __restrict__ out_idx) {
    __shared__ float am[2048];
    __shared__ float red[8];
    __shared__ float sv[256];
    __shared__ int   si[256];
    int l = blockIdx.x, t = threadIdx.x;
    int lane = t & 31, wid = t >> 5;
    float amv[8] = {0, 0, 0, 0, 0, 0, 0, 0};

    for (int h = 0; h < NH; h++) {
        float* row = g_S + ((size_t)h * Nn + l) * Nn;
        float vals[8];
        float mx = -FLT_MAX;
        #pragma unroll
        for (int i = 0; i < 8; i++) { vals[i] = row[t + i * 256]; mx = fmaxf(mx, vals[i]); }
        mx = warpMax(mx);
        if (lane == 0) red[wid] = mx;
        __syncthreads();
        mx = red[0];
        #pragma unroll
        for (int i = 1; i < 8; i++) mx = fmaxf(mx, red[i]);
        __syncthreads();
        float sum = 0.0f;
        #pragma unroll
        for (int i = 0; i < 8; i++) { vals[i] = __expf(vals[i] - mx); sum += vals[i]; }
        sum = warpSum(sum);
        if (lane == 0) red[wid] = sum;
        __syncthreads();
        sum = red[0];
        #pragma unroll
        for (int i = 1; i < 8; i++) sum += red[i];
        __syncthreads();
        float inv = 1.0f / sum;
        #pragma unroll
        for (int i = 0; i < 8; i++) {
            float a = vals[i] * inv;
            row[t + i * 256] = a;
            amv[i] += a;
        }
    }
    #pragma unroll
    for (int i = 0; i < 8; i++) am[t + i * 256] = amv[i] * 0.125f;
    __syncthreads();

    // iterative top-16 (ties -> lowest index, matching jax.lax.top_k)
    for (int j = 0; j < TOPK; j++) {
        float bv = -FLT_MAX; int bi = 0x7fffffff;
        #pragma unroll
        for (int i = 0; i < 8; i++) {
            int c = t + i * 256;
            float v = am[c];
            if (v > bv || (v == bv && c < bi)) { bv = v; bi = c; }
        }
        sv[t] = bv; si[t] = bi; __syncthreads();
        for (int s = 128; s > 0; s >>= 1) {
            if (t < s) {
                if (sv[t + s] > sv[t] || (sv[t + s] == sv[t] && si[t + s] < si[t])) {
                    sv[t] = sv[t + s]; si[t] = si[t + s];
                }
            }
            __syncthreads();
        }
        if (t == 0) {
            out_idx[l * TOPK + j] = (float)si[0];
            am[si[0]] = -FLT_MAX;
        }
        __syncthreads();
    }
}

// ---------------- per-head A @ V -> message --------------------------------
__global__ void av_kernel(const float* __restrict__ qkv) {
    __shared__ float At[64][64];
    __shared__ float Vt[64][32];
    int tid = threadIdx.x;
    int h = blockIdx.y, l0 = blockIdx.x * 64;
    int col = tid % 32, rg = tid / 32; // rg in [0,8)
    float acc[8] = {};
    for (int s0 = 0; s0 < Nn; s0 += 64) {
        for (int i = tid; i < 64 * 64; i += 256) {
            int r = i / 64, c = i % 64;
            At[r][c] = g_S[((size_t)h * Nn + l0 + r) * Nn + s0 + c];
        }
        for (int i = tid; i < 64 * 32; i += 256) {
            int s = i / 32, d = i % 32;
            Vt[s][d] = qkv[(s0 + s) * 768 + 512 + h * 32 + d];
        }
        __syncthreads();
        #pragma unroll
        for (int st = 0; st < 64; st++) {
            float vv = Vt[st][col];
            #pragma unroll
            for (int r = 0; r < 8; r++) acc[r] += At[rg * 8 + r][st] * vv;
        }
        __syncthreads();
    }
    #pragma unroll
    for (int r = 0; r < 8; r++)
        g_msg[(l0 + rg * 8 + r) * 256 + h * 32 + col] = acc[r];
}

// ---------------- launch ----------------------------------------------------
extern "C" void kernel_launch(void* const* d_in, const int* in_sizes, int n_in,
                              void* d_out, int out_size) {
    const float* point  = (const float*)d_in[0];
    const float* w_qkv  = (const float*)d_in[1];
    const float* w_proj = (const float*)d_in[2];
    const float* b_proj = (const float*)d_in[3];
    const float* n1w    = (const float*)d_in[4];
    const float* n1b    = (const float*)d_in[5];
    const float* n2w    = (const float*)d_in[6];
    const float* n2b    = (const float*)d_in[7];
    float* out = (float*)d_out;

    float *p_x, *p_qkv, *p_msg, *p_msg2;
    cudaGetSymbolAddress((void**)&p_x,    g_x);
    cudaGetSymbolAddress((void**)&p_qkv,  g_qkv);
    cudaGetSymbolAddress((void**)&p_msg,  g_msg);
    cudaGetSymbolAddress((void**)&p_msg2, g_msg2);

    // 1. LN1
    ln_kernel<<<Nn, 256>>>(point, n1w, n1b, p_x);
    // 2. QKV GEMM: [2048,256] @ [256,768]
    sgemm_qkv<<<dim3(768 / 64, Nn / 64), 256>>>(p_x, w_qkv, p_qkv, Nn, 256, 768);
    // 3. per-head scores (128x128 tiles)
    qk_kernel<<<dim3(Nn / 128, Nn / 128, NH), 256>>>(p_qkv);
    // 4. fused softmax + head-mean + top-16 (writes indices region of d_out)
    softmax_mean_topk<<<Nn, 256>>>(out + Nn * DIM);
    // 5. A @ V
    av_kernel<<<dim3(Nn / 64, NH), 256>>>(p_qkv);
    // 6. proj + bias + residual(v)
    sgemm_proj<<<dim3(256 / 64, Nn / 64), 256>>>(p_msg, w_proj, b_proj, p_qkv, p_msg2);
    // 7. LN2 -> main output region
    ln_kernel<<<Nn, 256>>>(p_msg2, n2w, n2b, out);
}